// round 16
// baseline (speedup 1.0000x reference)
#include <cuda_runtime.h>
#include <cuda_fp16.h>
#include <math.h>
#include <float.h>

#define MAX_NODES 100000
#define MAX_EDGES 1600000
#define SCAN_TILE 1024
#define MAX_SCAN_BLOCKS 128

// Scratch — referenced directly from device code.
// g_bufA: fp16 GEMM outputs (gather operand). g_bufB: fp16 spmm outputs
// (layers 0,1) feeding the next GEMM; final layer writes fp32 d_out.
__device__ __align__(16) float g_bufA[MAX_NODES * 64];
__device__ __align__(16) float g_bufB[MAX_NODES * 64];
__device__ __align__(16) int g_deg_out[MAX_NODES];
__device__ __align__(16) int g_deg_in[MAX_NODES];
__device__ int   g_rowptr[MAX_NODES + 1];
__device__ int   g_cursor[MAX_NODES];
__device__ int   g_col[MAX_EDGES];
__device__ __align__(16) float g_ns[MAX_NODES];
__device__ __align__(16) float g_nd[MAX_NODES];
__device__ int g_scan_status[MAX_SCAN_BLOCKS];   // 0 invalid / 1 partial / 2 prefix
__device__ int g_scan_partial[MAX_SCAN_BLOCKS];
__device__ int g_scan_prefix[MAX_SCAN_BLOCKS];

// Register-only fp16x2 -> float2 (no address-of -> no spills).
__device__ __forceinline__ float2 h2f2(unsigned v) {
    float2 f;
    asm("{\n\t.reg .b16 lo, hi;\n\t"
        "mov.b32 {lo, hi}, %2;\n\t"
        "cvt.f32.f16 %0, lo;\n\t"
        "cvt.f32.f16 %1, hi;\n\t}"
        : "=f"(f.x), "=f"(f.y) : "r"(v));
    return f;
}

__device__ __forceinline__ unsigned smem_u32(const void* p) {
    unsigned a;
    asm("{ .reg .u64 t; cvta.to.shared.u64 t, %1; cvt.u32.u64 %0, t; }"
        : "=r"(a) : "l"(p));
    return a;
}

__device__ __forceinline__ void ldsm_x4(unsigned* a, unsigned addr) {
    asm volatile("ldmatrix.sync.aligned.m8n8.x4.shared.b16 {%0,%1,%2,%3}, [%4];"
        : "=r"(a[0]), "=r"(a[1]), "=r"(a[2]), "=r"(a[3]) : "r"(addr));
}
__device__ __forceinline__ void ldsm_x2t(unsigned* b, unsigned addr) {
    asm volatile("ldmatrix.sync.aligned.m8n8.x2.trans.shared.b16 {%0,%1}, [%2];"
        : "=r"(b[0]), "=r"(b[1]) : "r"(addr));
}
__device__ __forceinline__ void mma_f16(float* c, const unsigned* a, const unsigned* b) {
    asm volatile("mma.sync.aligned.m16n8k16.row.col.f32.f16.f16.f32 "
        "{%0,%1,%2,%3}, {%4,%5,%6,%7}, {%8,%9}, {%0,%1,%2,%3};"
        : "+f"(c[0]), "+f"(c[1]), "+f"(c[2]), "+f"(c[3])
        : "r"(a[0]), "r"(a[1]), "r"(a[2]), "r"(a[3]), "r"(b[0]), "r"(b[1]));
}

// ---------------------------------------------------------------------------
// CSR build.
// ---------------------------------------------------------------------------
__global__ void zero_deg_kernel(int n) {
    int i = blockIdx.x * blockDim.x + threadIdx.x;
    if (i < n) { g_deg_out[i] = 0; g_deg_in[i] = 0; }
    if (i < MAX_SCAN_BLOCKS) g_scan_status[i] = 0;
}

__global__ void deg_kernel(const int* __restrict__ src,
                           const int* __restrict__ dst, int E) {
    int i = blockIdx.x * blockDim.x + threadIdx.x;
    if (i < E) {
        atomicAdd(&g_deg_out[src[i]], 1);
        atomicAdd(&g_deg_in[dst[i]], 1);
    }
}

__device__ __forceinline__ int warp_incl_scan(int v, int lane) {
#pragma unroll
    for (int o = 1; o < 32; o <<= 1) {
        int t = __shfl_up_sync(0xffffffffu, v, o);
        if (lane >= o) v += t;
    }
    return v;
}

__device__ __forceinline__ float deg_norm(int d) {
    return (d > 0) ? rsqrtf((float)d) : 0.0f;
}

// Single-pass decoupled-lookback exclusive scan of g_deg_in -> rowptr/cursor,
// fused with ns/nd. 98 blocks (all co-resident; blockIdx-ordered lookback safe).
__global__ void scan_lookback_kernel(int n, int nblocks) {
    __shared__ int woff[8];
    __shared__ int s_block_off;
    int tid = threadIdx.x, lane = tid & 31, wid = tid >> 5;
    int blk = blockIdx.x;
    int base = blk * SCAN_TILE + tid * 4;

    int4 v = make_int4(0, 0, 0, 0);
    if (base < n) v = *reinterpret_cast<const int4*>(&g_deg_in[base]);
    int s = v.x + v.y + v.z + v.w;
    int incl = warp_incl_scan(s, lane);
    if (lane == 31) woff[wid] = incl;
    __syncthreads();
    if (tid == 0) {
        int acc = 0;
#pragma unroll
        for (int w = 0; w < 8; w++) { int t = woff[w]; woff[w] = acc; acc += t; }
        // acc = block total. Publish partial.
        g_scan_partial[blk] = acc;
        __threadfence();
        atomicExch(&g_scan_status[blk], 1);
        // Lookback for exclusive block offset.
        int off = 0;
        for (int i = blk - 1; i >= 0;) {
            int st = atomicAdd(&g_scan_status[i], 0);
            if (st == 2) { __threadfence(); off += g_scan_prefix[i]; break; }
            if (st == 1) { __threadfence(); off += g_scan_partial[i]; i--; }
            // st == 0: spin
        }
        g_scan_prefix[blk] = off + acc;   // inclusive prefix
        __threadfence();
        atomicExch(&g_scan_status[blk], 2);
        s_block_off = off;
        if (blk == nblocks - 1) g_rowptr[n] = off + acc;
    }
    __syncthreads();

    if (base < n) {
        int excl = incl - s + woff[wid] + s_block_off;
        int p0 = excl, p1 = p0 + v.x, p2 = p1 + v.y, p3 = p2 + v.z;
        *reinterpret_cast<int4*>(&g_rowptr[base]) = make_int4(p0, p1, p2, p3);
        *reinterpret_cast<int4*>(&g_cursor[base]) = make_int4(p0, p1, p2, p3);
        int4 o = *reinterpret_cast<const int4*>(&g_deg_out[base]);
        *reinterpret_cast<float4*>(&g_ns[base]) =
            make_float4(deg_norm(o.x), deg_norm(o.y), deg_norm(o.z), deg_norm(o.w));
        *reinterpret_cast<float4*>(&g_nd[base]) =
            make_float4(deg_norm(v.x), deg_norm(v.y), deg_norm(v.z), deg_norm(v.w));
    }
}

__global__ void fill_kernel(const int* __restrict__ src,
                            const int* __restrict__ dst, int E) {
    int e = blockIdx.x * blockDim.x + threadIdx.x;
    if (e < E) {
        int d = dst[e];
        int pos = atomicAdd(&g_cursor[d], 1);
        g_col[pos] = src[e];
    }
}

// ---------------------------------------------------------------------------
// Tensor-core GEMM: halfA[M,N] = half((X[M,K] @ W[K,N]) [* g_ns[row]])
// A_HALF: A operand is fp16 (g_bufB from previous spmm), K must be 64.
// ---------------------------------------------------------------------------
template<int K, int N, bool SCALE_NS, bool A_HALF>
__global__ void __launch_bounds__(256) gemm_mma_kernel(
        const float* __restrict__ Xext, const float* __restrict__ W, int M) {
    __shared__ __half As[128 * 72];
    __shared__ __half Bs[K * 72];

    __half* outh = reinterpret_cast<__half*>(g_bufA);
    const int tid = threadIdx.x;
    const int lane = tid & 31;
    const int w = tid >> 5;
    const int wm = w & 3;
    const int wn = w >> 2;
    const int row0 = blockIdx.x * 128;

    for (int t = tid; t < K * 72; t += 256) {
        int k = t / 72, n = t - k * 72;
        Bs[t] = (n < N) ? __float2half(W[k * N + n]) : __float2half(0.0f);
    }

    const unsigned as_base = smem_u32(As);
    const unsigned bs_base = smem_u32(Bs);

    float c_[2][4][4];
#pragma unroll
    for (int mt = 0; mt < 2; mt++)
#pragma unroll
        for (int nt = 0; nt < 4; nt++)
#pragma unroll
            for (int j = 0; j < 4; j++) c_[mt][nt][j] = 0.0f;

    constexpr int NCHUNK = K / 64;
    for (int kc = 0; kc < NCHUNK; kc++) {
        __syncthreads();
        if (A_HALF) {
            // fp16 A: 128 rows x 64 halves = 8 uint4 (16B) chunks per row.
            const __half* Xh = reinterpret_cast<const __half*>(g_bufB);
            for (int t = tid; t < 128 * 8; t += 256) {
                int r = t >> 3, c = t & 7;
                int grow = row0 + r;
                uint4 u = make_uint4(0u, 0u, 0u, 0u);
                if (grow < M)
                    u = *reinterpret_cast<const uint4*>(&Xh[(size_t)grow * K + c * 8]);
                *reinterpret_cast<uint4*>(&As[r * 72 + c * 8]) = u;
            }
        } else {
            const float* X = Xext;
            for (int t = tid; t < 128 * 16; t += 256) {
                int r = t >> 4, c = t & 15;
                int grow = row0 + r;
                __half2 h0 = __floats2half2_rn(0.f, 0.f), h1 = h0;
                if (grow < M) {
                    float4 v = *reinterpret_cast<const float4*>(
                        &X[(size_t)grow * K + kc * 64 + c * 4]);
                    h0 = __floats2half2_rn(v.x, v.y);
                    h1 = __floats2half2_rn(v.z, v.w);
                }
                *reinterpret_cast<__half2*>(&As[r * 72 + c * 4]) = h0;
                *reinterpret_cast<__half2*>(&As[r * 72 + c * 4 + 2]) = h1;
            }
        }
        __syncthreads();

#pragma unroll
        for (int ks = 0; ks < 4; ks++) {
            int kglob = kc * 64 + ks * 16;
            unsigned a[2][4], b[4][2];
#pragma unroll
            for (int mt = 0; mt < 2; mt++) {
                unsigned addr = as_base +
                    (((wm * 32 + mt * 16 + (lane & 15)) * 72 + ks * 16 + (lane >> 4) * 8) * 2);
                ldsm_x4(a[mt], addr);
            }
#pragma unroll
            for (int nt = 0; nt < 4; nt++) {
                unsigned addr = bs_base +
                    (((kglob + (lane & 15)) * 72 + wn * 32 + nt * 8) * 2);
                ldsm_x2t(b[nt], addr);
            }
#pragma unroll
            for (int mt = 0; mt < 2; mt++)
#pragma unroll
                for (int nt = 0; nt < 4; nt++)
                    mma_f16(c_[mt][nt], a[mt], b[nt]);
        }
    }

#pragma unroll
    for (int mt = 0; mt < 2; mt++) {
#pragma unroll
        for (int nt = 0; nt < 4; nt++) {
            int r = wm * 32 + mt * 16 + (lane >> 2);
            int col = wn * 32 + nt * 8 + (lane & 3) * 2;
            if (col < N) {
                int g0 = row0 + r, g1 = g0 + 8;
                if (g0 < M) {
                    float s = SCALE_NS ? g_ns[g0] : 1.0f;
                    *reinterpret_cast<__half2*>(&outh[(size_t)g0 * N + col]) =
                        __floats2half2_rn(c_[mt][nt][0] * s, c_[mt][nt][1] * s);
                }
                if (g1 < M) {
                    float s = SCALE_NS ? g_ns[g1] : 1.0f;
                    *reinterpret_cast<__half2*>(&outh[(size_t)g1 * N + col]) =
                        __floats2half2_rn(c_[mt][nt][2] * s, c_[mt][nt][3] * s);
                }
            }
        }
    }
}

// ---------------------------------------------------------------------------
// Fused SpMM-gather (fp16 features, uint2 loads, fp32 accumulate) + nd + bias
// + [relu] + log_softmax. OUT_HALF: store result fp16 into g_bufB (feeds next
// GEMM); else fp32 into outp (final layer).
// ---------------------------------------------------------------------------
template<int F, bool RELU, bool APPLY_NS, bool OUT_HALF>
__global__ void __launch_bounds__(256) spmm_fused_kernel(
        const float* __restrict__ bias, int n, float* __restrict__ outp) {
    constexpr int CH = F / 4;
    constexpr int G = 32 / CH;

    int row = blockIdx.x * (blockDim.x >> 5) + (threadIdx.x >> 5);
    if (row >= n) return;
    int lane = threadIdx.x & 31;
    int g = lane / CH;
    int sub = lane - g * CH;

    const __half* hA = reinterpret_cast<const __half*>(g_bufA);

    int start = g_rowptr[row];
    int end = g_rowptr[row + 1];

    float4 acc = make_float4(0.f, 0.f, 0.f, 0.f);
    if (g < G) {
#pragma unroll 4
        for (int e = start + g; e < end; e += G) {
            int s = g_col[e];
            float w = APPLY_NS ? g_ns[s] : 1.0f;
            uint2 u = *reinterpret_cast<const uint2*>(hA + (long long)s * F + sub * 4);
            float2 f0 = h2f2(u.x);
            float2 f1 = h2f2(u.y);
            if (APPLY_NS) {
                acc.x = fmaf(w, f0.x, acc.x);
                acc.y = fmaf(w, f0.y, acc.y);
                acc.z = fmaf(w, f1.x, acc.z);
                acc.w = fmaf(w, f1.y, acc.w);
            } else {
                acc.x += f0.x; acc.y += f0.y; acc.z += f1.x; acc.w += f1.y;
            }
        }
    }

    float4 tot = acc;
#pragma unroll
    for (int k = 1; k < G; k++) {
        tot.x += __shfl_sync(0xffffffffu, acc.x, sub + k * CH);
        tot.y += __shfl_sync(0xffffffffu, acc.y, sub + k * CH);
        tot.z += __shfl_sync(0xffffffffu, acc.z, sub + k * CH);
        tot.w += __shfl_sync(0xffffffffu, acc.w, sub + k * CH);
    }

    float ndv = g_nd[row];
    float4 bv = *reinterpret_cast<const float4*>(bias + sub * 4);
    float4 x;
    x.x = tot.x * ndv + bv.x;
    x.y = tot.y * ndv + bv.y;
    x.z = tot.z * ndv + bv.z;
    x.w = tot.w * ndv + bv.w;
    if (RELU) {
        x.x = fmaxf(x.x, 0.f); x.y = fmaxf(x.y, 0.f);
        x.z = fmaxf(x.z, 0.f); x.w = fmaxf(x.w, 0.f);
    }

    bool valid = (lane < CH);
    float m = valid ? fmaxf(fmaxf(x.x, x.y), fmaxf(x.z, x.w)) : -FLT_MAX;
#pragma unroll
    for (int o = 8; o > 0; o >>= 1) m = fmaxf(m, __shfl_xor_sync(0xffffffffu, m, o));
    float s = valid ? (expf(x.x - m) + expf(x.y - m) + expf(x.z - m) + expf(x.w - m)) : 0.f;
#pragma unroll
    for (int o = 8; o > 0; o >>= 1) s += __shfl_xor_sync(0xffffffffu, s, o);
    float ls = m + logf(s);

    if (valid) {
        if (OUT_HALF) {
            __half* outh = reinterpret_cast<__half*>(g_bufB);
            __half2 h0 = __floats2half2_rn(x.x - ls, x.y - ls);
            __half2 h1 = __floats2half2_rn(x.z - ls, x.w - ls);
            __half2* p = reinterpret_cast<__half2*>(outh + (long long)row * F + sub * 4);
            p[0] = h0; p[1] = h1;
        } else {
            float4 r;
            r.x = x.x - ls; r.y = x.y - ls; r.z = x.z - ls; r.w = x.w - ls;
            *reinterpret_cast<float4*>(outp + (long long)row * F + sub * 4) = r;
        }
    }
}

// ---------------------------------------------------------------------------
// Launch — single stream, 10 launches (capture window lands on mainline work).
// ---------------------------------------------------------------------------
extern "C" void kernel_launch(void* const* d_in, const int* in_sizes, int n_in,
                              void* d_out, int out_size) {
    const float* feats = (const float*)d_in[0];
    const int*   src   = (const int*)d_in[1];
    const int*   dst   = (const int*)d_in[2];
    const float* W0    = (const float*)d_in[3];
    const float* b0    = (const float*)d_in[4];
    const float* W1    = (const float*)d_in[5];
    const float* b1    = (const float*)d_in[6];
    const float* W2    = (const float*)d_in[7];
    const float* b2    = (const float*)d_in[8];

    int N = in_sizes[0] / 128;   // 100000
    int E = in_sizes[1];         // 1600000
    float* outp = (float*)d_out;

    int scan_blocks = (N + SCAN_TILE - 1) / SCAN_TILE;   // 98
    int spmm_blocks = (N + 7) / 8;
    int gemm_blocks = (N + 127) / 128;

    // ---- CSR build ----
    zero_deg_kernel<<<(N + 255) / 256, 256>>>(N);
    deg_kernel<<<(E + 255) / 256, 256>>>(src, dst, E);
    scan_lookback_kernel<<<scan_blocks, 256>>>(N, scan_blocks);
    fill_kernel<<<(E + 255) / 256, 256>>>(src, dst, E);

    // ---- layer 0: 128 -> 64, relu, log_softmax (fp16 out) ----
    gemm_mma_kernel<128, 64, true, false><<<gemm_blocks, 256>>>(feats, W0, N);
    spmm_fused_kernel<64, true, false, true><<<spmm_blocks, 256>>>(b0, N, nullptr);

    // ---- layer 1: 64 -> 64, relu, log_softmax (fp16 out) ----
    gemm_mma_kernel<64, 64, true, true><<<gemm_blocks, 256>>>(nullptr, W1, N);
    spmm_fused_kernel<64, true, false, true><<<spmm_blocks, 256>>>(b1, N, nullptr);

    // ---- layer 2: 64 -> 40, no relu, log_softmax (fp32 -> d_out) ----
    gemm_mma_kernel<64, 40, true, true><<<gemm_blocks, 256>>>(nullptr, W2, N);
    spmm_fused_kernel<40, false, false, false><<<spmm_blocks, 256>>>(b2, N, outp);
}

// round 17
// speedup vs baseline: 1.0407x; 1.0407x over previous
#include <cuda_runtime.h>
#include <cuda_fp16.h>
#include <math.h>
#include <float.h>

#define MAX_NODES 100000
#define MAX_EDGES 1600000
#define SCAN_TILE 1024
#define MAX_SCAN_BLOCKS 128

// Scratch — referenced directly from device code.
// g_bufA: fp16 GEMM outputs (gather operand). g_bufB: fp16 spmm outputs.
__device__ __align__(16) float g_bufA[MAX_NODES * 64];
__device__ __align__(16) float g_bufB[MAX_NODES * 64];
__device__ __align__(16) int g_deg_out[MAX_NODES];
__device__ __align__(16) int g_deg_in[MAX_NODES];
__device__ int   g_rowptr[MAX_NODES + 1];
__device__ int   g_col[MAX_EDGES];
__device__ int   g_slot[MAX_EDGES];
__device__ __align__(16) float g_ns[MAX_NODES];
__device__ __align__(16) float g_nd[MAX_NODES];
__device__ int g_scan_status[MAX_SCAN_BLOCKS];
__device__ int g_scan_partial[MAX_SCAN_BLOCKS];
__device__ int g_scan_prefix[MAX_SCAN_BLOCKS];

// Register-only fp16x2 -> float2 (no address-of -> no spills).
__device__ __forceinline__ float2 h2f2(unsigned v) {
    float2 f;
    asm("{\n\t.reg .b16 lo, hi;\n\t"
        "mov.b32 {lo, hi}, %2;\n\t"
        "cvt.f32.f16 %0, lo;\n\t"
        "cvt.f32.f16 %1, hi;\n\t}"
        : "=f"(f.x), "=f"(f.y) : "r"(v));
    return f;
}

__device__ __forceinline__ unsigned smem_u32(const void* p) {
    unsigned a;
    asm("{ .reg .u64 t; cvta.to.shared.u64 t, %1; cvt.u32.u64 %0, t; }"
        : "=r"(a) : "l"(p));
    return a;
}

__device__ __forceinline__ void ldsm_x4(unsigned* a, unsigned addr) {
    asm volatile("ldmatrix.sync.aligned.m8n8.x4.shared.b16 {%0,%1,%2,%3}, [%4];"
        : "=r"(a[0]), "=r"(a[1]), "=r"(a[2]), "=r"(a[3]) : "r"(addr));
}
__device__ __forceinline__ void ldsm_x2t(unsigned* b, unsigned addr) {
    asm volatile("ldmatrix.sync.aligned.m8n8.x2.trans.shared.b16 {%0,%1}, [%2];"
        : "=r"(b[0]), "=r"(b[1]) : "r"(addr));
}
__device__ __forceinline__ void mma_f16(float* c, const unsigned* a, const unsigned* b) {
    asm volatile("mma.sync.aligned.m16n8k16.row.col.f32.f16.f16.f32 "
        "{%0,%1,%2,%3}, {%4,%5,%6,%7}, {%8,%9}, {%0,%1,%2,%3};"
        : "+f"(c[0]), "+f"(c[1]), "+f"(c[2]), "+f"(c[3])
        : "r"(a[0]), "r"(a[1]), "r"(a[2]), "r"(a[3]), "r"(b[0]), "r"(b[1]));
}

// ---------------------------------------------------------------------------
// CSR build — slot method (pass2 is atomic-free).
// ---------------------------------------------------------------------------
__global__ void zero_deg_kernel(int n) {
    int i = blockIdx.x * blockDim.x + threadIdx.x;
    if (i < n) { g_deg_out[i] = 0; g_deg_in[i] = 0; }
    if (i < MAX_SCAN_BLOCKS) g_scan_status[i] = 0;
}

// Pass 1: count out-degrees + claim per-dst slot (3.2M atomics total).
__global__ void edge_pass1_kernel(const int* __restrict__ src,
                                  const int* __restrict__ dst, int E) {
    int i = blockIdx.x * blockDim.x + threadIdx.x;
    if (i < E) {
        atomicAdd(&g_deg_out[src[i]], 1);
        g_slot[i] = atomicAdd(&g_deg_in[dst[i]], 1);
    }
}

__device__ __forceinline__ int warp_incl_scan(int v, int lane) {
#pragma unroll
    for (int o = 1; o < 32; o <<= 1) {
        int t = __shfl_up_sync(0xffffffffu, v, o);
        if (lane >= o) v += t;
    }
    return v;
}

__device__ __forceinline__ float deg_norm(int d) {
    return (d > 0) ? rsqrtf((float)d) : 0.0f;
}

// Single-pass decoupled-lookback exclusive scan of g_deg_in -> rowptr + norms.
__global__ void scan_lookback_kernel(int n, int nblocks) {
    __shared__ int woff[8];
    __shared__ int s_block_off;
    int tid = threadIdx.x, lane = tid & 31, wid = tid >> 5;
    int blk = blockIdx.x;
    int base = blk * SCAN_TILE + tid * 4;

    int4 v = make_int4(0, 0, 0, 0);
    if (base < n) v = *reinterpret_cast<const int4*>(&g_deg_in[base]);
    int s = v.x + v.y + v.z + v.w;
    int incl = warp_incl_scan(s, lane);
    if (lane == 31) woff[wid] = incl;
    __syncthreads();
    if (tid == 0) {
        int acc = 0;
#pragma unroll
        for (int w = 0; w < 8; w++) { int t = woff[w]; woff[w] = acc; acc += t; }
        g_scan_partial[blk] = acc;
        __threadfence();
        atomicExch(&g_scan_status[blk], 1);
        int off = 0;
        for (int i = blk - 1; i >= 0;) {
            int st = atomicAdd(&g_scan_status[i], 0);
            if (st == 2) { __threadfence(); off += g_scan_prefix[i]; break; }
            if (st == 1) { __threadfence(); off += g_scan_partial[i]; i--; }
        }
        g_scan_prefix[blk] = off + acc;
        __threadfence();
        atomicExch(&g_scan_status[blk], 2);
        s_block_off = off;
        if (blk == nblocks - 1) g_rowptr[n] = off + acc;
    }
    __syncthreads();

    if (base < n) {
        int excl = incl - s + woff[wid] + s_block_off;
        int p0 = excl, p1 = p0 + v.x, p2 = p1 + v.y, p3 = p2 + v.z;
        *reinterpret_cast<int4*>(&g_rowptr[base]) = make_int4(p0, p1, p2, p3);
        int4 o = *reinterpret_cast<const int4*>(&g_deg_out[base]);
        *reinterpret_cast<float4*>(&g_ns[base]) =
            make_float4(deg_norm(o.x), deg_norm(o.y), deg_norm(o.z), deg_norm(o.w));
        *reinterpret_cast<float4*>(&g_nd[base]) =
            make_float4(deg_norm(v.x), deg_norm(v.y), deg_norm(v.z), deg_norm(v.w));
    }
}

// Pass 2: atomic-free scatter using precomputed slots.
__global__ void edge_pass2_kernel(const int* __restrict__ src,
                                  const int* __restrict__ dst, int E) {
    int i = blockIdx.x * blockDim.x + threadIdx.x;
    if (i < E) {
        int d = dst[i];
        g_col[g_rowptr[d] + g_slot[i]] = src[i];
    }
}

// ---------------------------------------------------------------------------
// Tensor-core GEMM: halfA[M,N] = half((X[M,K] @ W[K,N]) [* g_ns[row]])
// A_HALF: A operand is fp16 (g_bufB from previous spmm), K must be 64.
// ---------------------------------------------------------------------------
template<int K, int N, bool SCALE_NS, bool A_HALF>
__global__ void __launch_bounds__(256) gemm_mma_kernel(
        const float* __restrict__ Xext, const float* __restrict__ W, int M) {
    __shared__ __half As[128 * 72];
    __shared__ __half Bs[K * 72];

    __half* outh = reinterpret_cast<__half*>(g_bufA);
    const int tid = threadIdx.x;
    const int lane = tid & 31;
    const int w = tid >> 5;
    const int wm = w & 3;
    const int wn = w >> 2;
    const int row0 = blockIdx.x * 128;

    for (int t = tid; t < K * 72; t += 256) {
        int k = t / 72, n = t - k * 72;
        Bs[t] = (n < N) ? __float2half(W[k * N + n]) : __float2half(0.0f);
    }

    const unsigned as_base = smem_u32(As);
    const unsigned bs_base = smem_u32(Bs);

    float c_[2][4][4];
#pragma unroll
    for (int mt = 0; mt < 2; mt++)
#pragma unroll
        for (int nt = 0; nt < 4; nt++)
#pragma unroll
            for (int j = 0; j < 4; j++) c_[mt][nt][j] = 0.0f;

    constexpr int NCHUNK = K / 64;
    for (int kc = 0; kc < NCHUNK; kc++) {
        __syncthreads();
        if (A_HALF) {
            const __half* Xh = reinterpret_cast<const __half*>(g_bufB);
            for (int t = tid; t < 128 * 8; t += 256) {
                int r = t >> 3, c = t & 7;
                int grow = row0 + r;
                uint4 u = make_uint4(0u, 0u, 0u, 0u);
                if (grow < M)
                    u = *reinterpret_cast<const uint4*>(&Xh[(size_t)grow * K + c * 8]);
                *reinterpret_cast<uint4*>(&As[r * 72 + c * 8]) = u;
            }
        } else {
            const float* X = Xext;
            for (int t = tid; t < 128 * 16; t += 256) {
                int r = t >> 4, c = t & 15;
                int grow = row0 + r;
                __half2 h0 = __floats2half2_rn(0.f, 0.f), h1 = h0;
                if (grow < M) {
                    float4 v = *reinterpret_cast<const float4*>(
                        &X[(size_t)grow * K + kc * 64 + c * 4]);
                    h0 = __floats2half2_rn(v.x, v.y);
                    h1 = __floats2half2_rn(v.z, v.w);
                }
                *reinterpret_cast<__half2*>(&As[r * 72 + c * 4]) = h0;
                *reinterpret_cast<__half2*>(&As[r * 72 + c * 4 + 2]) = h1;
            }
        }
        __syncthreads();

#pragma unroll
        for (int ks = 0; ks < 4; ks++) {
            int kglob = kc * 64 + ks * 16;
            unsigned a[2][4], b[4][2];
#pragma unroll
            for (int mt = 0; mt < 2; mt++) {
                unsigned addr = as_base +
                    (((wm * 32 + mt * 16 + (lane & 15)) * 72 + ks * 16 + (lane >> 4) * 8) * 2);
                ldsm_x4(a[mt], addr);
            }
#pragma unroll
            for (int nt = 0; nt < 4; nt++) {
                unsigned addr = bs_base +
                    (((kglob + (lane & 15)) * 72 + wn * 32 + nt * 8) * 2);
                ldsm_x2t(b[nt], addr);
            }
#pragma unroll
            for (int mt = 0; mt < 2; mt++)
#pragma unroll
                for (int nt = 0; nt < 4; nt++)
                    mma_f16(c_[mt][nt], a[mt], b[nt]);
        }
    }

#pragma unroll
    for (int mt = 0; mt < 2; mt++) {
#pragma unroll
        for (int nt = 0; nt < 4; nt++) {
            int r = wm * 32 + mt * 16 + (lane >> 2);
            int col = wn * 32 + nt * 8 + (lane & 3) * 2;
            if (col < N) {
                int g0 = row0 + r, g1 = g0 + 8;
                if (g0 < M) {
                    float s = SCALE_NS ? g_ns[g0] : 1.0f;
                    *reinterpret_cast<__half2*>(&outh[(size_t)g0 * N + col]) =
                        __floats2half2_rn(c_[mt][nt][0] * s, c_[mt][nt][1] * s);
                }
                if (g1 < M) {
                    float s = SCALE_NS ? g_ns[g1] : 1.0f;
                    *reinterpret_cast<__half2*>(&outh[(size_t)g1 * N + col]) =
                        __floats2half2_rn(c_[mt][nt][2] * s, c_[mt][nt][3] * s);
                }
            }
        }
    }
}

// ---------------------------------------------------------------------------
// Fused SpMM-gather (fp16 features, uint2 loads, fp32 accumulate) + nd + bias
// + [relu] + log_softmax. OUT_HALF: fp16 -> g_bufB; else fp32 -> outp.
// ---------------------------------------------------------------------------
template<int F, bool RELU, bool APPLY_NS, bool OUT_HALF>
__global__ void __launch_bounds__(256) spmm_fused_kernel(
        const float* __restrict__ bias, int n, float* __restrict__ outp) {
    constexpr int CH = F / 4;
    constexpr int G = 32 / CH;

    int row = blockIdx.x * (blockDim.x >> 5) + (threadIdx.x >> 5);
    if (row >= n) return;
    int lane = threadIdx.x & 31;
    int g = lane / CH;
    int sub = lane - g * CH;

    const __half* hA = reinterpret_cast<const __half*>(g_bufA);

    int start = g_rowptr[row];
    int end = g_rowptr[row + 1];

    float4 acc = make_float4(0.f, 0.f, 0.f, 0.f);
    if (g < G) {
#pragma unroll 4
        for (int e = start + g; e < end; e += G) {
            int s = g_col[e];
            float w = APPLY_NS ? g_ns[s] : 1.0f;
            uint2 u = *reinterpret_cast<const uint2*>(hA + (long long)s * F + sub * 4);
            float2 f0 = h2f2(u.x);
            float2 f1 = h2f2(u.y);
            if (APPLY_NS) {
                acc.x = fmaf(w, f0.x, acc.x);
                acc.y = fmaf(w, f0.y, acc.y);
                acc.z = fmaf(w, f1.x, acc.z);
                acc.w = fmaf(w, f1.y, acc.w);
            } else {
                acc.x += f0.x; acc.y += f0.y; acc.z += f1.x; acc.w += f1.y;
            }
        }
    }

    float4 tot = acc;
#pragma unroll
    for (int k = 1; k < G; k++) {
        tot.x += __shfl_sync(0xffffffffu, acc.x, sub + k * CH);
        tot.y += __shfl_sync(0xffffffffu, acc.y, sub + k * CH);
        tot.z += __shfl_sync(0xffffffffu, acc.z, sub + k * CH);
        tot.w += __shfl_sync(0xffffffffu, acc.w, sub + k * CH);
    }

    float ndv = g_nd[row];
    float4 bv = *reinterpret_cast<const float4*>(bias + sub * 4);
    float4 x;
    x.x = tot.x * ndv + bv.x;
    x.y = tot.y * ndv + bv.y;
    x.z = tot.z * ndv + bv.z;
    x.w = tot.w * ndv + bv.w;
    if (RELU) {
        x.x = fmaxf(x.x, 0.f); x.y = fmaxf(x.y, 0.f);
        x.z = fmaxf(x.z, 0.f); x.w = fmaxf(x.w, 0.f);
    }

    bool valid = (lane < CH);
    float m = valid ? fmaxf(fmaxf(x.x, x.y), fmaxf(x.z, x.w)) : -FLT_MAX;
#pragma unroll
    for (int o = 8; o > 0; o >>= 1) m = fmaxf(m, __shfl_xor_sync(0xffffffffu, m, o));
    float s = valid ? (expf(x.x - m) + expf(x.y - m) + expf(x.z - m) + expf(x.w - m)) : 0.f;
#pragma unroll
    for (int o = 8; o > 0; o >>= 1) s += __shfl_xor_sync(0xffffffffu, s, o);
    float ls = m + logf(s);

    if (valid) {
        if (OUT_HALF) {
            __half* outh = reinterpret_cast<__half*>(g_bufB);
            __half2 h0 = __floats2half2_rn(x.x - ls, x.y - ls);
            __half2 h1 = __floats2half2_rn(x.z - ls, x.w - ls);
            __half2* p = reinterpret_cast<__half2*>(outh + (long long)row * F + sub * 4);
            p[0] = h0; p[1] = h1;
        } else {
            float4 r;
            r.x = x.x - ls; r.y = x.y - ls; r.z = x.z - ls; r.w = x.w - ls;
            *reinterpret_cast<float4*>(outp + (long long)row * F + sub * 4) = r;
        }
    }
}

// ---------------------------------------------------------------------------
// Launch. CSR build on side stream (fork/join), GEMM0 overlaps it.
// ---------------------------------------------------------------------------
extern "C" void kernel_launch(void* const* d_in, const int* in_sizes, int n_in,
                              void* d_out, int out_size) {
    const float* feats = (const float*)d_in[0];
    const int*   src   = (const int*)d_in[1];
    const int*   dst   = (const int*)d_in[2];
    const float* W0    = (const float*)d_in[3];
    const float* b0    = (const float*)d_in[4];
    const float* W1    = (const float*)d_in[5];
    const float* b1    = (const float*)d_in[6];
    const float* W2    = (const float*)d_in[7];
    const float* b2    = (const float*)d_in[8];

    int N = in_sizes[0] / 128;   // 100000
    int E = in_sizes[1];         // 1600000
    float* outp = (float*)d_out;

    static cudaStream_t s1 = nullptr;
    static cudaEvent_t evFork = nullptr, evJoin = nullptr;
    if (s1 == nullptr) {
        cudaStreamCreateWithFlags(&s1, cudaStreamNonBlocking);
        cudaEventCreateWithFlags(&evFork, cudaEventDisableTiming);
        cudaEventCreateWithFlags(&evJoin, cudaEventDisableTiming);
    }

    int scan_blocks = (N + SCAN_TILE - 1) / SCAN_TILE;   // 98
    int spmm_blocks = (N + 7) / 8;
    int gemm_blocks = (N + 127) / 128;

    // ---- fork: CSR build on side stream ----
    cudaEventRecord(evFork, 0);
    cudaStreamWaitEvent(s1, evFork, 0);
    zero_deg_kernel<<<(N + 255) / 256, 256, 0, s1>>>(N);
    edge_pass1_kernel<<<(E + 255) / 256, 256, 0, s1>>>(src, dst, E);
    scan_lookback_kernel<<<scan_blocks, 256, 0, s1>>>(N, scan_blocks);
    edge_pass2_kernel<<<(E + 255) / 256, 256, 0, s1>>>(src, dst, E);
    cudaEventRecord(evJoin, s1);

    // ---- concurrently: layer-0 GEMM (ns applied in spmm0 instead) ----
    gemm_mma_kernel<128, 64, false, false><<<gemm_blocks, 256>>>(feats, W0, N);

    // ---- join, then layer-0 gather applies ns per edge ----
    cudaStreamWaitEvent(0, evJoin, 0);
    spmm_fused_kernel<64, true, true, true><<<spmm_blocks, 256>>>(b0, N, nullptr);

    // ---- layer 1: 64 -> 64, relu, log_softmax (fp16 out) ----
    gemm_mma_kernel<64, 64, true, true><<<gemm_blocks, 256>>>(nullptr, W1, N);
    spmm_fused_kernel<64, true, false, true><<<spmm_blocks, 256>>>(b1, N, nullptr);

    // ---- layer 2: 64 -> 40, no relu, log_softmax (fp32 -> d_out) ----
    gemm_mma_kernel<64, 40, true, true><<<gemm_blocks, 256>>>(nullptr, W2, N);
    spmm_fused_kernel<40, false, false, false><<<spmm_blocks, 256>>>(b2, N, outp);
}